// round 5
// baseline (speedup 1.0000x reference)
#include <cuda_runtime.h>
#include <math.h>
#include <float.h>

// Geometry
#define NROWS   131072
#define KCODE   512
#define BCH     262144           // 64*64*64 batch stride in z (B,C,H,W)
#define NTILES  2048             // NROWS / 64
#define GRID    148

// d_out layout (fp32, outputs concatenated)
#define OFF_LOSS 0
#define OFF_ZQ   1
#define OFF_PERP 8388609
#define OFF_ENC  8388610ULL
#define OFF_CODE 75497474ULL

// smem layout (float offsets)
#define S_ZT   0        // [4096]  z tile: zt[(p*64+r)*2 + (d&1)], p=d>>1
#define S_WP   4096     // [32768] weight: wp[d*512 + c]
#define S_WN   36864    // [512]
#define S_ZN   37376    // [64]
#define S_PART 37440    // [256f] = 128 u64 argmin partials
#define S_CODE 37696    // [64]   int rowcode
#define S_HIST 37760    // [512]  int
#define S_LRED 38272    // [16]
#define S_TOT  38288

__device__ float g_loss_part[GRID];
__device__ int   g_hist_part[GRID * KCODE];

__device__ __forceinline__ unsigned long long packbb(float x) {
    unsigned long long r;
    asm("mov.b64 %0, {%1,%1};" : "=l"(r) : "f"(x));
    return r;
}
__device__ __forceinline__ void unpack2(unsigned long long a, float& lo, float& hi) {
    asm("mov.b64 {%0,%1}, %2;" : "=f"(lo), "=f"(hi) : "l"(a));
}
__device__ __forceinline__ void lds128(unsigned long long& a, unsigned long long& b,
                                       unsigned addr) {
    asm("ld.shared.v2.u64 {%0,%1}, [%2];" : "=l"(a), "=l"(b) : "r"(addr));
}
__device__ __forceinline__ unsigned long long lds64(unsigned addr) {
    unsigned long long v;
    asm("ld.shared.u64 %0, [%1];" : "=l"(v) : "r"(addr));
    return v;
}
__device__ __forceinline__ void ffma2(unsigned long long& acc,
                                      unsigned long long a, unsigned long long b) {
    asm("fma.rn.f32x2 %0, %1, %2, %0;" : "+l"(acc) : "l"(a), "l"(b));
}
__device__ __forceinline__ unsigned orderable(float s) {
    unsigned ub = __float_as_uint(s);
    return (ub & 0x80000000u) ? ~ub : (ub | 0x80000000u);
}

__global__ __launch_bounds__(512, 1)
void vq_gemm(const float* __restrict__ z, const float* __restrict__ w,
             float* __restrict__ dout) {
    extern __shared__ float sm[];
    float*              zt   = sm + S_ZT;
    float*              wp   = sm + S_WP;
    float*              wn   = sm + S_WN;
    float*              zn   = sm + S_ZN;
    unsigned long long* part = (unsigned long long*)(sm + S_PART);
    int*                rcd  = (int*)(sm + S_CODE);
    int*                hist = (int*)(sm + S_HIST);
    float*              lred = sm + S_LRED;

    const int tid = threadIdx.x;
    const int n   = tid & 63;          // code-pair thread
    const int mth = tid >> 6;          // row group thread (0..7)

    // stage weight: wp[d*512 + c] = w[c*64 + d]
    for (int idx = tid; idx < 32768; idx += 512) {
        int c = idx >> 6, d = idx & 63;
        wp[d * 512 + c] = w[idx];
    }
    hist[tid] = 0;
    __syncthreads();

    // wn[c]: strict sequential sum of rounded squares (reference order)
    {
        float v = wp[tid];
        float s = __fmul_rn(v, v);
#pragma unroll
        for (int d = 1; d < 64; ++d) {
            v = wp[d * 512 + tid];
            s = __fadd_rn(s, __fmul_rn(v, v));
        }
        wn[tid] = s;
    }

    const unsigned smbase = (unsigned)__cvta_generic_to_shared(sm);
    const unsigned zbA    = smbase + S_ZT * 4 + mth * 64;
    const unsigned wbB    = smbase + S_WP * 4 + n * 8;

    float ls = 0.0f;

    for (int tile = blockIdx.x; tile < NTILES; tile += GRID) {
        __syncthreads();   // zt/rcd reuse barrier (prev tile epilogue done)
        const int    n0  = tile * 64;
        const int    b   = n0 >> 12;
        const int    rem = n0 & 4095;
        const float* zg  = z + (size_t)b * BCH + rem;

        // stage z tile (64 rows x 64 dims), pair layout
#pragma unroll
        for (int pass = 0; pass < 8; ++pass) {
            int d = pass * 8 + (tid >> 6);
            int r = tid & 63;
            zt[((d >> 1) * 64 + r) * 2 + (d & 1)] = zg[((size_t)d << 12) + r];
        }
        __syncthreads();

        // zn[r]: strict sequential (reference order)
        if (tid < 64) {
            float v = zt[tid * 2];
            float s = __fmul_rn(v, v);
#pragma unroll
            for (int d = 1; d < 64; ++d) {
                v = zt[((d >> 1) * 64 + tid) * 2 + (d & 1)];
                s = __fadd_rn(s, __fmul_rn(v, v));
            }
            zn[tid] = s;
        }
        __syncthreads();   // zn visible before per-half epilogues

        unsigned long long key[8];
#pragma unroll
        for (int i = 0; i < 8; ++i) key[i] = 0xFFFFFFFFFFFFFFFFULL;

#pragma unroll
        for (int half = 0; half < 2; ++half) {
            unsigned long long acc[16];
#pragma unroll
            for (int q = 0; q < 16; ++q) acc[q] = 0ULL;
            const unsigned wbH = wbB + (unsigned)half * 1024u;

#pragma unroll 4
            for (int p = 0; p < 32; ++p) {
                unsigned long long za[8];
#pragma unroll
                for (int q = 0; q < 4; ++q)
                    lds128(za[2 * q], za[2 * q + 1],
                           zbA + (unsigned)p * 512u + (unsigned)q * 16u);
                unsigned long long wb0[2], wb1[2];
#pragma unroll
                for (int j = 0; j < 2; ++j) {
                    unsigned a = wbH + (unsigned)p * 4096u + (unsigned)j * 512u;
                    wb0[j] = lds64(a);
                    wb1[j] = lds64(a + 2048u);
                }
#pragma unroll
                for (int i = 0; i < 8; ++i) {
                    float lo, hi;
                    unpack2(za[i], lo, hi);
                    unsigned long long dl = packbb(lo);
                    unsigned long long dh = packbb(hi);
#pragma unroll
                    for (int j = 0; j < 2; ++j) {
                        ffma2(acc[i * 2 + j], dl, wb0[j]);   // dim 2p
                        ffma2(acc[i * 2 + j], dh, wb1[j]);   // dim 2p+1
                    }
                }
            }

            // per-half epilogue: exact score pipeline, update keys
#pragma unroll
            for (int i = 0; i < 8; ++i) {
                float znr = zn[mth * 8 + i];
#pragma unroll
                for (int j = 0; j < 2; ++j) {
                    float lo, hi;
                    unpack2(acc[i * 2 + j], lo, hi);
                    int c0 = 2 * (n + 64 * j + 128 * half);
                    float s0 = __fsub_rn(__fadd_rn(znr, wn[c0]),     __fadd_rn(lo, lo));
                    float s1 = __fsub_rn(__fadd_rn(znr, wn[c0 + 1]), __fadd_rn(hi, hi));
                    unsigned long long k0 =
                        ((unsigned long long)orderable(s0) << 32) | (unsigned)c0;
                    unsigned long long k1 =
                        ((unsigned long long)orderable(s1) << 32) | (unsigned)(c0 + 1);
                    if (k0 < key[i]) key[i] = k0;
                    if (k1 < key[i]) key[i] = k1;
                }
            }
        }

        // warp argmin reduce (2 warps per row-group)
#pragma unroll
        for (int i = 0; i < 8; ++i) {
            unsigned long long k = key[i];
#pragma unroll
            for (int off = 16; off > 0; off >>= 1) {
                unsigned long long o = __shfl_down_sync(0xFFFFFFFFu, k, off);
                if (o < k) k = o;
            }
            if ((tid & 31) == 0) part[(mth * 8 + i) * 2 + ((tid >> 5) & 1)] = k;
        }
        __syncthreads();

        if (tid < 64) {
            unsigned long long k0 = part[tid * 2], k1 = part[tid * 2 + 1];
            if (k1 < k0) k0 = k1;
            int code = (int)(unsigned)(k0 & 0xFFFFFFFFULL);
            rcd[tid] = code;
            dout[OFF_CODE + (size_t)(n0 + tid)] = (float)code;
            atomicAdd(&hist[code], 1);
        }
        __syncthreads();

        // zq + loss (coalesced by dim)
        float* zqg = dout + OFF_ZQ + (size_t)b * BCH + rem;
#pragma unroll
        for (int pass = 0; pass < 8; ++pass) {
            int d = pass * 8 + (tid >> 6);
            int r = tid & 63;
            int code = rcd[r];
            float zv = zt[((d >> 1) * 64 + r) * 2 + (d & 1)];
            float wv = wp[d * 512 + code];
            float df = __fsub_rn(wv, zv);
            ls = fmaf(df, df, ls);
            zqg[((size_t)d << 12) + r] = __fadd_rn(zv, df);
        }

        // encodings one-hot (268 MB total; overlaps next tile's FMAs)
        float2* encp = (float2*)(dout + OFF_ENC);
#pragma unroll
        for (int pass = 0; pass < 32; ++pass) {
            int e  = pass * 512 + tid;
            int r  = e >> 8;
            int c2 = e & 255;
            int code = rcd[r];
            float2 v = make_float2(0.0f, 0.0f);
            if (c2 == (code >> 1)) { if (code & 1) v.y = 1.0f; else v.x = 1.0f; }
            encp[(size_t)(n0 + r) * 256 + c2] = v;
        }
    }

    // per-block partials (no cross-launch state, no init kernel needed)
    __syncthreads();
    const int lane = tid & 31, wid = tid >> 5;
    float lw = ls;
#pragma unroll
    for (int off = 16; off > 0; off >>= 1)
        lw += __shfl_down_sync(0xFFFFFFFFu, lw, off);
    if (lane == 0) lred[wid] = lw;
    __syncthreads();
    if (tid == 0) {
        float t = 0.0f;
#pragma unroll
        for (int i = 0; i < 16; ++i) t += lred[i];
        g_loss_part[blockIdx.x] = t;
    }
    g_hist_part[blockIdx.x * KCODE + tid] = hist[tid];
}

__global__ void vq_final(float* __restrict__ dout) {
    __shared__ float sred[16];
    int t = threadIdx.x;  // 512
    int cnt = 0;
    for (int bb = 0; bb < GRID; ++bb) cnt += g_hist_part[bb * KCODE + t];
    float em = (float)cnt * (1.0f / 131072.0f);
    float v  = em * logf(__fadd_rn(em, 1e-10f));
    int lane = t & 31, wid = t >> 5;
#pragma unroll
    for (int off = 16; off > 0; off >>= 1)
        v += __shfl_down_sync(0xFFFFFFFFu, v, off);
    if (lane == 0) sred[wid] = v;
    __syncthreads();
    if (wid == 0) {
        float s = (lane < 16) ? sred[lane] : 0.0f;
#pragma unroll
        for (int off = 8; off > 0; off >>= 1)
            s += __shfl_down_sync(0xFFFFFFFFu, s, off);
        if (lane == 0) dout[OFF_PERP] = expf(-s);
    }
    if (wid == 1) {   // loss: sum 148 block partials
        float s = 0.0f;
        for (int i = lane; i < GRID; i += 32) s += g_loss_part[i];
#pragma unroll
        for (int off = 16; off > 0; off >>= 1)
            s += __shfl_down_sync(0xFFFFFFFFu, s, off);
        if (lane == 0) {
            float m = s * (1.0f / 8388608.0f);
            dout[OFF_LOSS] = __fadd_rn(m, __fmul_rn(0.25f, m));
        }
    }
}

extern "C" void kernel_launch(void* const* d_in, const int* in_sizes, int n_in,
                              void* d_out, int out_size) {
    const float* z = (const float*)d_in[0];
    const float* w = (const float*)d_in[1];
    float* out = (float*)d_out;

    const int smem_bytes = S_TOT * 4;
    cudaFuncSetAttribute(vq_gemm, cudaFuncAttributeMaxDynamicSharedMemorySize,
                         smem_bytes);

    vq_gemm<<<GRID, 512, smem_bytes>>>(z, w, out);
    vq_final<<<1, 512>>>(out);
}